// round 10
// baseline (speedup 1.0000x reference)
#include <cuda_runtime.h>
#include <cstdint>

// Problem constants
#define NTOK   16384
#define DDIM   2048
#define NEXP   64
#define TOPK   8
#define ROUTE_SCALE 2.5f

// Tiling
#define BM     128          // tokens per CTA
#define KC     16           // k-chunk (2 mma k-steps)
#define CHUNKS (DDIM / KC)  // 128
#define KPAD   20           // A row stride in floats (16B-aligned, conflict-free)

// Packed-W layout: per chunk c, per expert e, 8 float4 quads:
//   quad(e, kk2, tg) = { wh[e][c*16+kk2*8+tg], wh[..+tg+4], wl[..+tg], wl[..+tg+4] }
// stored at a16 = e*8 + ((kk2 ^ (e&1))<<2) + tg   (swizzle -> LDS.128 conflict-free)
// Global image = per-chunk contiguous 512 quads (8 KB).
__device__ float4 g_wpack[CHUNKS * 512];   // 1 MB

struct SmemPipe {
    float  A[2][BM][KPAD];      // 20480 B
    float4 B[2][512];           // 16384 B
};
struct SmemEpi {
    float sc[BM][NEXP + 1];     // stride 65 -> conflict-free
    float bias[NEXP];
};
union SmemU { SmemPipe p; SmemEpi e; };

__device__ __forceinline__ unsigned cvt_tf32(float x) {
    unsigned r;
    asm("cvt.rna.tf32.f32 %0, %1;" : "=r"(r) : "f"(x));
    return r;
}
// exact hi/lo split: hi is a valid fp32 (low 13 mantissa bits zero), a-hi exact
__device__ __forceinline__ void split_tf32(float a, unsigned& hi, unsigned& lo) {
    hi = cvt_tf32(a);
    lo = cvt_tf32(a - __uint_as_float(hi));
}

__device__ __forceinline__ void cp_async16(void* smem_ptr, const void* gmem_ptr) {
    unsigned s = (unsigned)__cvta_generic_to_shared(smem_ptr);
    asm volatile("cp.async.cg.shared.global [%0], [%1], 16;\n"
                 :: "r"(s), "l"(gmem_ptr) : "memory");
}
__device__ __forceinline__ void cp_commit() {
    asm volatile("cp.async.commit_group;\n" ::: "memory");
}

__device__ __forceinline__ void mma_tf32(float c[4], unsigned a0, unsigned a1,
                                         unsigned a2, unsigned a3,
                                         unsigned b0, unsigned b1) {
    asm volatile(
        "mma.sync.aligned.m16n8k8.row.col.f32.tf32.tf32.f32 "
        "{%0,%1,%2,%3}, {%4,%5,%6,%7}, {%8,%9}, {%0,%1,%2,%3};\n"
        : "+f"(c[0]), "+f"(c[1]), "+f"(c[2]), "+f"(c[3])
        : "r"(a0), "r"(a1), "r"(a2), "r"(a3), "r"(b0), "r"(b1));
}

// Accurate fp32 exp (Cephes), ~1 ulp, independent of -use_fast_math.
// Valid for |x| <= ~20 (logits here are |x| <= ~4).
__device__ __forceinline__ float exp_acc(float x) {
    float n = rintf(x * 1.44269504088896341f);
    float r = fmaf(n, -0.693359375f, x);          // ln2_hi (exact product)
    r = fmaf(n, 2.12194440e-4f, r);               // + n*(ln2_hi - ln2)
    float p = 1.9875691500E-4f;
    p = fmaf(p, r, 1.3981999507E-3f);
    p = fmaf(p, r, 8.3334519073E-3f);
    p = fmaf(p, r, 4.1665795894E-2f);
    p = fmaf(p, r, 1.6666665459E-1f);
    p = fmaf(p, r, 5.0000001201E-1f);
    float res = fmaf(p, r * r, r) + 1.0f;
    return res * __int_as_float(((int)n + 127) << 23);
}
__device__ __forceinline__ float sigmoid_acc(float z) {
    return __frcp_rn(1.0f + exp_acc(-z));          // correctly-rounded 1/(1+e^-z)
}

// ---------------- pre-kernel: split + pack W ----------------
__global__ void pack_w_kernel(const float* __restrict__ w) {
    int d = blockIdx.x * blockDim.x + threadIdx.x;   // quad index, 65536 total
    int tg  = d & 3;
    int s   = (d >> 2) & 1;
    int e   = (d >> 3) & 63;
    int c   = d >> 9;
    int kk2 = s ^ (e & 1);
    const float* base = w + (size_t)e * DDIM + c * KC + kk2 * 8 + tg;
    float v0 = base[0], v1 = base[4];
    unsigned h0, l0, h1, l1;
    split_tf32(v0, h0, l0);
    split_tf32(v1, h1, l1);
    g_wpack[d] = make_float4(__uint_as_float(h0), __uint_as_float(h1),
                             __uint_as_float(l0), __uint_as_float(l1));
}

// ---------------- main kernel ----------------
__global__ __launch_bounds__(256, 1)
void expert_gate_kernel(const float* __restrict__ x,
                        const float* __restrict__ ebias,
                        float* __restrict__ out) {
    __shared__ __align__(16) SmemU sm;

    const int tid  = threadIdx.x;
    const int warp = tid >> 5;
    const int lane = tid & 31;
    const int m0   = blockIdx.x * BM;
    const int mrow = warp * 16;
    const int g    = lane >> 2;
    const int tg   = lane & 3;

    // per-lane constant B quad offsets (kstep 0 / 1)
    const int bq0 = g * 8 + (((0 ^ (g & 1))) << 2) + tg;
    const int bq1 = g * 8 + (((1 ^ (g & 1))) << 2) + tg;

    auto load_chunk = [&](int stage, int c) {
        const int k0 = c * KC;
#pragma unroll
        for (int i = 0; i < 2; ++i) {           // A: 512 quads
            int idx = tid + i * 256;
            int r   = idx >> 2;
            int c4  = idx & 3;
            cp_async16(&sm.p.A[stage][r][c4 * 4],
                       x + (size_t)(m0 + r) * DDIM + k0 + c4 * 4);
        }
#pragma unroll
        for (int i = 0; i < 2; ++i) {           // B: 512 packed quads
            int j = tid + i * 256;
            cp_async16(&sm.p.B[stage][j], &g_wpack[c * 512 + j]);
        }
    };

    // accs/comp: Kahan sum of main hi*hi term; accl: per-window local;
    // accc: cross terms (hi*lo + lo*hi), plain accumulation (2^-12 scaled).
    float accs[8][4], comp[8][4], accl[8][4], accc[8][4];
#pragma unroll
    for (int nt = 0; nt < 8; ++nt)
#pragma unroll
        for (int i = 0; i < 4; ++i) {
            accs[nt][i] = 0.f; comp[nt][i] = 0.f;
            accl[nt][i] = 0.f; accc[nt][i] = 0.f;
        }

    load_chunk(0, 0);
    cp_commit();

    for (int c = 0; c < CHUNKS; ++c) {
        if (c + 1 < CHUNKS) {
            load_chunk((c + 1) & 1, c + 1);
            cp_commit();
            asm volatile("cp.async.wait_group 1;\n" ::: "memory");
        } else {
            asm volatile("cp.async.wait_group 0;\n" ::: "memory");
        }
        __syncthreads();

        const int st = c & 1;
        const float4* __restrict__ Bst = sm.p.B[st];
#pragma unroll
        for (int kk2 = 0; kk2 < 2; ++kk2) {
            const int kk = kk2 * 8;
            unsigned ah0, al0, ah1, al1, ah2, al2, ah3, al3;
            split_tf32(sm.p.A[st][mrow + g    ][kk + tg    ], ah0, al0);
            split_tf32(sm.p.A[st][mrow + g + 8][kk + tg    ], ah1, al1);
            split_tf32(sm.p.A[st][mrow + g    ][kk + tg + 4], ah2, al2);
            split_tf32(sm.p.A[st][mrow + g + 8][kk + tg + 4], ah3, al3);
            const int bq = kk2 ? bq1 : bq0;
#pragma unroll
            for (int nt = 0; nt < 8; ++nt) {
                float4 q = Bst[nt * 64 + bq];
                unsigned bh0 = __float_as_uint(q.x);
                unsigned bh1 = __float_as_uint(q.y);
                unsigned bl0 = __float_as_uint(q.z);
                unsigned bl1 = __float_as_uint(q.w);
                mma_tf32(accl[nt], ah0, ah1, ah2, ah3, bh0, bh1); // main
                mma_tf32(accc[nt], ah0, ah1, ah2, ah3, bl0, bl1); // hi*lo
                mma_tf32(accc[nt], al0, al1, al2, al3, bh0, bh1); // lo*hi
            }
        }
        __syncthreads();

        if ((c & 3) == 3) {   // Kahan merge every 4 chunks
#pragma unroll
            for (int nt = 0; nt < 8; ++nt)
#pragma unroll
                for (int i = 0; i < 4; ++i) {
                    float y = accl[nt][i] - comp[nt][i];
                    float t = accs[nt][i] + y;
                    comp[nt][i] = (t - accs[nt][i]) - y;
                    accs[nt][i] = t;
                    accl[nt][i] = 0.f;
                }
        }
    }

    // ---- epilogue: combine, sigmoid, scores to smem ----
#pragma unroll
    for (int nt = 0; nt < 8; ++nt) {
        int r  = mrow + g;
        int cc = nt * 8 + tg * 2;
#pragma unroll
        for (int i = 0; i < 4; ++i) {
            float logit = accs[nt][i] + (accc[nt][i] - comp[nt][i]);
            float s = sigmoid_acc(logit);
            int rr = (i >= 2) ? r + 8 : r;
            sm.e.sc[rr][cc + (i & 1)] = s;
        }
    }
    if (tid < NEXP) sm.e.bias[tid] = ebias[tid];
    __syncthreads();

    // ---- per-token biased top-8 ----
    if (tid < BM) {
        const int t = tid;
        float val[TOPK];
        int   idx[TOPK];
#pragma unroll
        for (int j = 0; j < TOPK; ++j) { val[j] = -1e30f; idx[j] = 0; }

#pragma unroll
        for (int e = 0; e < NEXP; ++e) {
            float v  = sm.e.sc[t][e] + sm.e.bias[e];
            int   id = e;
            // strict > keeps lower index first on ties (matches lax.top_k)
#pragma unroll
            for (int j = 0; j < TOPK; ++j) {
                bool take = v > val[j];
                float tv = val[j]; int ti = idx[j];
                if (take) { val[j] = v; idx[j] = id; v = tv; id = ti; }
            }
        }

        float s[TOPK];
        float sum = 0.0f;
#pragma unroll
        for (int j = 0; j < TOPK; ++j) {
            s[j] = sm.e.sc[t][idx[j]];
            sum += s[j];
        }
        const float sumb = sum + 1e-8f;

        const size_t gt = (size_t)(m0 + t);
        float* wout = out;
        float* iout = out + (size_t)NTOK * TOPK;   // indices as float values
#pragma unroll
        for (int j = 0; j < TOPK; ++j) {
            // mimic ref: (s / (sum+eps)) * 2.5, correctly-rounded division
            wout[gt * TOPK + j] = __fdiv_rn(s[j], sumb) * ROUTE_SCALE;
            iout[gt * TOPK + j] = (float)idx[j];
        }
    }
}

extern "C" void kernel_launch(void* const* d_in, const int* in_sizes, int n_in,
                              void* d_out, int out_size) {
    const float* x     = (const float*)d_in[0];   // (16384, 2048) f32
    const float* wgt   = (const float*)d_in[1];   // (64, 2048)    f32
    const float* ebias = (const float*)d_in[2];   // (64,)         f32
    float* out = (float*)d_out;

    pack_w_kernel<<<CHUNKS * 512 / 256, 256>>>(wgt);
    expert_gate_kernel<<<NTOK / BM, 256>>>(x, ebias, out);
}

// round 13
// speedup vs baseline: 1.0156x; 1.0156x over previous
#include <cuda_runtime.h>
#include <cstdint>

// Problem constants
#define NTOK   16384
#define DDIM   2048
#define NEXP   64
#define TOPK   8
#define ROUTE_SCALE 2.5f

// Tiling
#define BM     64           // tokens per CTA (experts split across warp halves)
#define KC     16           // k-chunk (2 mma k-steps)
#define CHUNKS (DDIM / KC)  // 128
#define KPAD   20           // A row stride in floats (16B-aligned, conflict-free)

// Packed-W layout (unchanged from R9): per chunk c, per expert e, 8 float4 quads:
//   quad(e, kk2, tg) = { wh[e][c*16+kk2*8+tg], wh[..+tg+4], wl[..+tg], wl[..+tg+4] }
// stored at a16 = e*8 + ((kk2 ^ (e&1))<<2) + tg   (swizzle -> LDS.128 conflict-free)
__device__ float4 g_wpack[CHUNKS * 512];   // 1 MB

struct SmemPipe {
    float  A[2][BM][KPAD];      // 2*64*20*4 = 10240 B
    float4 B[2][512];           // 16384 B
};
struct SmemEpi {
    float sc[BM][NEXP + 1];     // stride 65 -> conflict-free
    float bias[NEXP];
};
union SmemU { SmemPipe p; SmemEpi e; };

__device__ __forceinline__ unsigned cvt_tf32(float x) {
    unsigned r;
    asm("cvt.rna.tf32.f32 %0, %1;" : "=r"(r) : "f"(x));
    return r;
}
// exact hi/lo split: hi is a valid fp32 (low 13 mantissa bits zero), a-hi exact
__device__ __forceinline__ void split_tf32(float a, unsigned& hi, unsigned& lo) {
    hi = cvt_tf32(a);
    lo = cvt_tf32(a - __uint_as_float(hi));
}

__device__ __forceinline__ void cp_async16(void* smem_ptr, const void* gmem_ptr) {
    unsigned s = (unsigned)__cvta_generic_to_shared(smem_ptr);
    asm volatile("cp.async.cg.shared.global [%0], [%1], 16;\n"
                 :: "r"(s), "l"(gmem_ptr) : "memory");
}
__device__ __forceinline__ void cp_commit() {
    asm volatile("cp.async.commit_group;\n" ::: "memory");
}

__device__ __forceinline__ void mma_tf32(float c[4], unsigned a0, unsigned a1,
                                         unsigned a2, unsigned a3,
                                         unsigned b0, unsigned b1) {
    asm volatile(
        "mma.sync.aligned.m16n8k8.row.col.f32.tf32.tf32.f32 "
        "{%0,%1,%2,%3}, {%4,%5,%6,%7}, {%8,%9}, {%0,%1,%2,%3};\n"
        : "+f"(c[0]), "+f"(c[1]), "+f"(c[2]), "+f"(c[3])
        : "r"(a0), "r"(a1), "r"(a2), "r"(a3), "r"(b0), "r"(b1));
}

// Accurate fp32 exp (Cephes), ~1 ulp, flag-independent. |x| small here.
__device__ __forceinline__ float exp_acc(float x) {
    float n = rintf(x * 1.44269504088896341f);
    float r = fmaf(n, -0.693359375f, x);
    r = fmaf(n, 2.12194440e-4f, r);
    float p = 1.9875691500E-4f;
    p = fmaf(p, r, 1.3981999507E-3f);
    p = fmaf(p, r, 8.3334519073E-3f);
    p = fmaf(p, r, 4.1665795894E-2f);
    p = fmaf(p, r, 1.6666665459E-1f);
    p = fmaf(p, r, 5.0000001201E-1f);
    float res = fmaf(p, r * r, r) + 1.0f;
    return res * __int_as_float(((int)n + 127) << 23);
}
__device__ __forceinline__ float sigmoid_acc(float z) {
    return __frcp_rn(1.0f + exp_acc(-z));
}

// ---------------- pre-kernel: split + pack W (unchanged) ----------------
__global__ void pack_w_kernel(const float* __restrict__ w) {
    int d = blockIdx.x * blockDim.x + threadIdx.x;   // quad index, 65536 total
    int tg  = d & 3;
    int s   = (d >> 2) & 1;
    int e   = (d >> 3) & 63;
    int c   = d >> 9;
    int kk2 = s ^ (e & 1);
    const float* base = w + (size_t)e * DDIM + c * KC + kk2 * 8 + tg;
    float v0 = base[0], v1 = base[4];
    unsigned h0, l0, h1, l1;
    split_tf32(v0, h0, l0);
    split_tf32(v1, h1, l1);
    g_wpack[d] = make_float4(__uint_as_float(h0), __uint_as_float(h1),
                             __uint_as_float(l0), __uint_as_float(l1));
}

// ---------------- main kernel ----------------
// 8 warps: warp = (ew, mw); ew = warp>>2 selects expert half (0-31 / 32-63),
// mw = warp&3 selects 16-row slice. Per-token/per-expert arithmetic (K order,
// Kahan cadence, epilogue) is bit-identical to the R9 passing kernel; only the
// M/N work distribution changed, which cuts regs 195 -> ~120 and enables
// 2 CTAs/SM.
__global__ __launch_bounds__(256, 2)
void expert_gate_kernel(const float* __restrict__ x,
                        const float* __restrict__ ebias,
                        float* __restrict__ out) {
    __shared__ __align__(16) SmemU sm;

    const int tid  = threadIdx.x;
    const int warp = tid >> 5;
    const int lane = tid & 31;
    const int m0   = blockIdx.x * BM;
    const int mrow = (warp & 3) * 16;
    const int eoff = (warp >> 2) * 32;     // expert half offset
    const int g    = lane >> 2;
    const int tg   = lane & 3;

    // per-lane constant B quad offsets (kstep 0 / 1), relative to expert row g
    const int bq0 = g * 8 + (((0 ^ (g & 1))) << 2) + tg;
    const int bq1 = g * 8 + (((1 ^ (g & 1))) << 2) + tg;
    const int bbase = eoff * 8;            // 8 quads per expert row

    auto load_chunk = [&](int stage, int c) {
        const int k0 = c * KC;
        {                                   // A: 256 quads (64 rows x 4)
            int r  = tid >> 2;
            int c4 = tid & 3;
            cp_async16(&sm.p.A[stage][r][c4 * 4],
                       x + (size_t)(m0 + r) * DDIM + k0 + c4 * 4);
        }
#pragma unroll
        for (int i = 0; i < 2; ++i) {       // B: 512 packed quads
            int j = tid + i * 256;
            cp_async16(&sm.p.B[stage][j], &g_wpack[c * 512 + j]);
        }
    };

    // accs/comp: Kahan sum of main hi*hi term; accl: per-window local;
    // accc: cross terms. nt now spans 4 (32 experts per warp).
    float accs[4][4], comp[4][4], accl[4][4], accc[4][4];
#pragma unroll
    for (int nt = 0; nt < 4; ++nt)
#pragma unroll
        for (int i = 0; i < 4; ++i) {
            accs[nt][i] = 0.f; comp[nt][i] = 0.f;
            accl[nt][i] = 0.f; accc[nt][i] = 0.f;
        }

    load_chunk(0, 0);
    cp_commit();

    for (int c = 0; c < CHUNKS; ++c) {
        if (c + 1 < CHUNKS) {
            load_chunk((c + 1) & 1, c + 1);
            cp_commit();
            asm volatile("cp.async.wait_group 1;\n" ::: "memory");
        } else {
            asm volatile("cp.async.wait_group 0;\n" ::: "memory");
        }
        __syncthreads();

        const int st = c & 1;
        const float4* __restrict__ Bst = sm.p.B[st];
#pragma unroll
        for (int kk2 = 0; kk2 < 2; ++kk2) {
            const int kk = kk2 * 8;
            unsigned ah0, al0, ah1, al1, ah2, al2, ah3, al3;
            split_tf32(sm.p.A[st][mrow + g    ][kk + tg    ], ah0, al0);
            split_tf32(sm.p.A[st][mrow + g + 8][kk + tg    ], ah1, al1);
            split_tf32(sm.p.A[st][mrow + g    ][kk + tg + 4], ah2, al2);
            split_tf32(sm.p.A[st][mrow + g + 8][kk + tg + 4], ah3, al3);
            const int bq = (kk2 ? bq1 : bq0) + bbase;
#pragma unroll
            for (int nt = 0; nt < 4; ++nt) {
                float4 q = Bst[nt * 64 + bq];
                unsigned bh0 = __float_as_uint(q.x);
                unsigned bh1 = __float_as_uint(q.y);
                unsigned bl0 = __float_as_uint(q.z);
                unsigned bl1 = __float_as_uint(q.w);
                mma_tf32(accl[nt], ah0, ah1, ah2, ah3, bh0, bh1); // main
                mma_tf32(accc[nt], ah0, ah1, ah2, ah3, bl0, bl1); // hi*lo
                mma_tf32(accc[nt], al0, al1, al2, al3, bh0, bh1); // lo*hi
            }
        }
        __syncthreads();

        if ((c & 3) == 3) {   // Kahan merge every 4 chunks (same cadence as R9)
#pragma unroll
            for (int nt = 0; nt < 4; ++nt)
#pragma unroll
                for (int i = 0; i < 4; ++i) {
                    float y = accl[nt][i] - comp[nt][i];
                    float t = accs[nt][i] + y;
                    comp[nt][i] = (t - accs[nt][i]) - y;
                    accs[nt][i] = t;
                    accl[nt][i] = 0.f;
                }
        }
    }

    // ---- epilogue: combine, sigmoid, scores to smem ----
#pragma unroll
    for (int nt = 0; nt < 4; ++nt) {
        int r  = mrow + g;
        int cc = eoff + nt * 8 + tg * 2;
#pragma unroll
        for (int i = 0; i < 4; ++i) {
            float logit = accs[nt][i] + (accc[nt][i] - comp[nt][i]);
            float s = sigmoid_acc(logit);
            int rr = (i >= 2) ? r + 8 : r;
            sm.e.sc[rr][cc + (i & 1)] = s;
        }
    }
    if (tid < NEXP) sm.e.bias[tid] = ebias[tid];
    __syncthreads();

    // ---- per-token biased top-8 (one thread per token) ----
    if (tid < BM) {
        const int t = tid;
        float val[TOPK];
        int   idx[TOPK];
#pragma unroll
        for (int j = 0; j < TOPK; ++j) { val[j] = -1e30f; idx[j] = 0; }

#pragma unroll
        for (int e = 0; e < NEXP; ++e) {
            float v  = sm.e.sc[t][e] + sm.e.bias[e];
            int   id = e;
            // strict > keeps lower index first on ties (matches lax.top_k)
#pragma unroll
            for (int j = 0; j < TOPK; ++j) {
                bool take = v > val[j];
                float tv = val[j]; int ti = idx[j];
                if (take) { val[j] = v; idx[j] = id; v = tv; id = ti; }
            }
        }

        float s[TOPK];
        float sum = 0.0f;
#pragma unroll
        for (int j = 0; j < TOPK; ++j) {
            s[j] = sm.e.sc[t][idx[j]];
            sum += s[j];
        }
        const float sumb = sum + 1e-8f;

        const size_t gt = (size_t)(m0 + t);
        float* wout = out;
        float* iout = out + (size_t)NTOK * TOPK;   // indices as float values
#pragma unroll
        for (int j = 0; j < TOPK; ++j) {
            wout[gt * TOPK + j] = __fdiv_rn(s[j], sumb) * ROUTE_SCALE;
            iout[gt * TOPK + j] = (float)idx[j];
        }
    }
}

extern "C" void kernel_launch(void* const* d_in, const int* in_sizes, int n_in,
                              void* d_out, int out_size) {
    const float* x     = (const float*)d_in[0];   // (16384, 2048) f32
    const float* wgt   = (const float*)d_in[1];   // (64, 2048)    f32
    const float* ebias = (const float*)d_in[2];   // (64,)         f32
    float* out = (float*)d_out;

    pack_w_kernel<<<CHUNKS * 512 / 256, 256>>>(wgt);
    expert_gate_kernel<<<NTOK / BM, 256>>>(x, ebias, out);
}